// round 5
// baseline (speedup 1.0000x reference)
#include <cuda_runtime.h>
#include <cuda_fp16.h>

#define BB 2
#define LL 16
#define CC 16
#define HH 64
#define WW 64
#define HW (HH*WW)

// Channel-last fp16 image cache: pixel chunk = 32B (16 halves) = 2 uint4.
// Index: ((bl*HW + y*WW + x) * 2 + half_chunk)
__device__ uint4 g_imgH[BB*LL*HW*2];

// ---------------------------------------------------------------------------
// Kernel 1: transpose images (B,L,C,H,W) fp32 -> channel-last fp16
// ---------------------------------------------------------------------------
__global__ __launch_bounds__(256) void trans_kernel(const float* __restrict__ images) {
    int i = blockIdx.x * 256 + threadIdx.x;     // [0, BB*LL*HW)
    int bl  = i >> 12;
    int pix = i & (HW - 1);
    const float* s = images + (size_t)bl * CC * HW + pix;

    unsigned int u[8];
#pragma unroll
    for (int c = 0; c < 8; c++) {
        float f0 = s[(2 * c + 0) * HW];
        float f1 = s[(2 * c + 1) * HW];
        __half2 hh = __floats2half2_rn(f0, f1);
        u[c] = *(unsigned int*)&hh;
    }
    uint4* d = g_imgH + (size_t)i * 2;
    d[0] = make_uint4(u[0], u[1], u[2], u[3]);
    d[1] = make_uint4(u[4], u[5], u[6], u[7]);
}

// ---------------------------------------------------------------------------
// Per-(pixel,k) body: one lane handles all 16 channels, all 4 corners.
// x-columns combined in half2 (2 fp16 roundings), rows combined in fp32.
// ---------------------------------------------------------------------------
__device__ __forceinline__ void body(float relx, float rely, float bx, float by,
                                     const uint4* __restrict__ kb, float* acc) {
    float gx = bx + relx;
    float gy = by + rely;

    // wrap: mod(g+1, 2) - 1, then safety clamp (matches reference)
    float ux = gx + 1.0f; ux -= floorf(ux * 0.5f) * 2.0f; gx = ux - 1.0f;
    if (gx < -1.0f) gx += 2.0f;
    float uy = gy + 1.0f; uy -= floorf(uy * 0.5f) * 2.0f; gy = uy - 1.0f;
    if (gy < -1.0f) gy += 2.0f;

    float rx = (gx + 1.0f) * 0.5f * (float)WW - 0.5f;
    float ry = (gy + 1.0f) * 0.5f * (float)HH - 0.5f;

    float fx0 = floorf(rx), fy0 = floorf(ry);
    int x0 = (int)fx0, y0 = (int)fy0;          // in [-1, 63]
    float sx = rx - fx0, ax = 1.0f - sx;
    float sy = ry - fy0, ay = 1.0f - sy;

    float xl = (x0 >= 0)      ? ax : 0.0f;
    float xr = (x0 < WW - 1)  ? sx : 0.0f;
    float yt = (y0 >= 0)      ? ay : 0.0f;
    float yb = (y0 < HH - 1)  ? sy : 0.0f;

    __half2 wxl = __float2half2_rn(xl);
    __half2 wxr = __float2half2_rn(xr);

    int x0c = max(x0, 0), x1c = min(x0 + 1, WW - 1);
    int y0c = max(y0, 0), y1c = min(y0 + 1, HH - 1);

    const uint4* t0 = kb + (y0c * WW + x0c) * 2;
    const uint4* t1 = kb + (y0c * WW + x1c) * 2;
    const uint4* b0 = kb + (y1c * WW + x0c) * 2;
    const uint4* b1 = kb + (y1c * WW + x1c) * 2;

    uint4 vt0[2] = { t0[0], t0[1] };
    uint4 vt1[2] = { t1[0], t1[1] };
    uint4 vb0[2] = { b0[0], b0[1] };
    uint4 vb1[2] = { b1[0], b1[1] };

#pragma unroll
    for (int q = 0; q < 2; q++) {
        const unsigned int* pt0 = &vt0[q].x;
        const unsigned int* pt1 = &vt1[q].x;
        const unsigned int* pb0 = &vb0[q].x;
        const unsigned int* pb1 = &vb1[q].x;
#pragma unroll
        for (int j = 0; j < 4; j++) {
            __half2 ht = __hfma2(*(const __half2*)&pt1[j], wxr,
                                 __hmul2(*(const __half2*)&pt0[j], wxl));
            __half2 hb = __hfma2(*(const __half2*)&pb1[j], wxr,
                                 __hmul2(*(const __half2*)&pb0[j], wxl));
            float2 ft = __half22float2(ht);
            float2 fb = __half22float2(hb);
            int e = (q * 4 + j) * 2;
            acc[e + 0] += yt * ft.x + yb * fb.x;
            acc[e + 1] += yt * ft.y + yb * fb.y;
        }
    }
}

// ---------------------------------------------------------------------------
// Kernel 2: main. Block = 64 threads = 64 pixels (one image row) for one b.
// Each block computes TWO timesteps paired (ta = 15-r, tb = r) so every
// block does exactly ta+tb+2 = 17 k-iterations -> uniform load, single wave.
// Cumsum of flows fused per block into smem.
// ---------------------------------------------------------------------------
__global__ __launch_bounds__(64) void main_kernel(const float* __restrict__ flows,
                                                  float* __restrict__ out) {
    __shared__ float2 scum[LL * 64];   // [l][pixel], 8KB

    int idx  = blockIdx.x;
    int pblk = idx & 63;              // pixel row
    int r    = (idx >> 6) & 7;        // pair index
    int b    = idx >> 9;
    int ta   = 15 - r;
    int tb   = r;
    int p_base = pblk * 64;
    int pl = threadIdx.x;
    int p  = p_base + pl;

    // Fused cumsum: each thread owns one pixel, both components.
    {
        const float* fb = flows + (size_t)b * LL * 2 * HW + p_base + pl;
        float cx = 0.0f, cy = 0.0f;
#pragma unroll
        for (int l = 0; l < LL; l++) {
            cx += fb[(l * 2 + 0) * HW];
            cy += fb[(l * 2 + 1) * HW];
            scum[l * 64 + pl] = make_float2(cx, cy);
        }
    }
    __syncthreads();

    int h = p >> 6;
    int w = p & 63;
    float bx = (w + 0.5f) * (2.0f / WW) - 1.0f;
    float by = (h + 0.5f) * (2.0f / HH) - 1.0f;

    const uint4* ib = g_imgH + (size_t)b * LL * HW * 2;

#pragma unroll
    for (int pass = 0; pass < 2; pass++) {
        int t = pass ? tb : ta;
        float2 ct = scum[t * 64 + pl];

        float acc[16];
#pragma unroll
        for (int e = 0; e < 16; e++) acc[e] = 0.0f;

#pragma unroll 1
        for (int k = 0; k <= t; k++) {
            float2 ck = scum[k * 64 + pl];
            body(ct.x - ck.x, ct.y - ck.y, bx, by, ib + (size_t)k * HW * 2, acc);
        }

        // out layout (B,L,C,H,W)
        float* ob = out + (size_t)((b * LL + t) * CC) * HW + p;
#pragma unroll
        for (int c = 0; c < 16; c++) ob[c * HW] = acc[c];
    }
}

// ---------------------------------------------------------------------------
extern "C" void kernel_launch(void* const* d_in, const int* in_sizes, int n_in,
                              void* d_out, int out_size) {
    const float* flows  = (const float*)d_in[0];
    const float* images = (const float*)d_in[1];
    if (n_in >= 2 && in_sizes[0] > in_sizes[1]) {   // defensive: flows is smaller
        const float* tmp = flows; flows = images; images = tmp;
    }
    float* out = (float*)d_out;

    trans_kernel<<<BB * LL * HW / 256, 256>>>(images);
    main_kernel<<<BB * 8 * 64, 64>>>(flows, out);
}

// round 7
// speedup vs baseline: 1.4517x; 1.4517x over previous
#include <cuda_runtime.h>
#include <cuda_fp16.h>

#define BB 2
#define LL 16
#define CC 16
#define HH 64
#define WW 64
#define HW (HH*WW)

#define PW 68                 // padded width in 32B pixel-chunks; 68*32 = 2176 = 17*128 (rows 128B-aligned)
#define PH 66                 // padded height (rows -1..64)
#define PCH (PW*PH)           // 4488 chunks per image
#define IMG_BYTES (PCH*32)    // 143616

// Zero-padded channel-last fp16 image cache. Chunk (y,x) = 16 halves (32B) at
// chunk index (y+1)*PW + (x+1), for x,y in [-1,64].
__device__ uint4 g_pad[BB*LL*PCH*2];

// ---------------------------------------------------------------------------
// Kernel 1: images (B,L,C,H,W) fp32 -> padded channel-last fp16 (zero border)
// ---------------------------------------------------------------------------
__global__ __launch_bounds__(256) void pad_kernel(const float* __restrict__ images) {
    int i = blockIdx.x * 256 + threadIdx.x;      // [0, BB*LL*PCH)
    int bl = i / PCH;
    int s  = i - bl * PCH;
    int y  = s / PW;
    int x  = s - y * PW;
    uint4 v0 = make_uint4(0u,0u,0u,0u), v1 = v0;
    if (x >= 1 && x <= WW && y >= 1 && y <= HH) {
        int px = (y - 1) * WW + (x - 1);
        const float* sp = images + (size_t)bl * CC * HW + px;
        unsigned u[8];
#pragma unroll
        for (int c = 0; c < 8; c++) {
            __half2 hh = __floats2half2_rn(sp[(2*c) * HW], sp[(2*c+1) * HW]);
            u[c] = *(unsigned*)&hh;
        }
        v0 = make_uint4(u[0], u[1], u[2], u[3]);
        v1 = make_uint4(u[4], u[5], u[6], u[7]);
    }
    uint4* d = g_pad + (size_t)i * 2;
    d[0] = v0;
    d[1] = v1;
}

// ---------------------------------------------------------------------------
// Kernel 2: main. 4 lanes per pixel: q = (xq<<1)|cq (contiguous 64B per row
// span across the 4 lanes -> minimal L1 wavefronts given random flows).
// Padded image removes all masks/clamps; wrap done as one mod in pixel space;
// top/bottom combined with fp16 weights.
// ---------------------------------------------------------------------------
__global__ __launch_bounds__(256) void main_kernel(const float* __restrict__ flows,
                                                   float* __restrict__ out) {
    __shared__ float2 scum[LL * 64];

    int bt  = blockIdx.x >> 6;        // 64 blocks per (b,t), 64 pixels each
    int blk = blockIdx.x & 63;
    int b   = bt >> 4;
    int t   = 15 - (bt & 15);         // heavy blocks first
    int p_base = blk * 64;
    int tid = threadIdx.x;

    // Fused cumsum: threads 0..127 = 64 pixels x 2 components.
    if (tid < 128) {
        int comp = tid >> 6;
        int pl   = tid & 63;
        const float* fb = flows + ((size_t)b * LL * 2 + comp) * HW + p_base + pl;
        float c = 0.0f;
#pragma unroll
        for (int l = 0; l < LL; l++) {
            c += fb[l * 2 * HW];
            ((float*)&scum[l * 64 + pl])[comp] = c;
        }
    }
    __syncthreads();

    int pl = tid >> 2;
    int q  = tid & 3;
    int xq = q >> 1;                  // left/right column
    int cq = q & 1;                   // channel octet
    int p  = p_base + pl;
    int h  = p >> 6;
    int w  = p & 63;

    float2 ct = scum[t * 64 + pl];
    // uxp(k) = (w+0.5) + 32*(ct.x - ck.x) ; hoist the ct part
    float cwx = (w + 0.5f) + 32.0f * ct.x;
    float cwy = (h + 0.5f) + 32.0f * ct.y;

    float acc[8] = {0.f,0.f,0.f,0.f,0.f,0.f,0.f,0.f};

    // base: (b) image series + (+1,+1) pad offset + lane's column/octet offset
    const char* kb = (const char*)g_pad
                   + (size_t)(b * LL) * IMG_BYTES
                   + (size_t)((PW + 1 + xq) * 32 + cq * 16);

    for (int k = 0; k <= t; k++, kb += IMG_BYTES) {
        float2 ck = scum[k * 64 + pl];
        float uxp = fmaf(-32.0f, ck.x, cwx);
        float uyp = fmaf(-32.0f, ck.y, cwy);
        // mod into [0, 64): rxm = uxp - floor(uxp/64)*64   (== true rx + 0.5)
        float rxm = fmaf(-floorf(uxp * 0.015625f), 64.0f, uxp);
        float rym = fmaf(-floorf(uyp * 0.015625f), 64.0f, uyp);
        float rx0 = rxm - 0.5f;
        float ry0 = rym - 0.5f;
        float fx0 = floorf(rx0);
        float fy0 = floorf(ry0);
        int x0 = (int)fx0;            // [-1, 63]
        int y0 = (int)fy0;
        float sx = rx0 - fx0;
        float sy = ry0 - fy0;
        float axw = 1.0f - sx;
        float ayw = 1.0f - sy;

        float xw = xq ? sx : axw;     // this lane's column weight
        __half2 wt2 = __float2half2_rn(xw * ayw);
        __half2 wb2 = __float2half2_rn(xw * sy);

        const char* addr = kb + (y0 * PW + x0) * 32;
        uint4 top = *(const uint4*)(addr);
        uint4 bot = *(const uint4*)(addr + PW * 32);

        const __half2* tp = (const __half2*)&top;
        const __half2* bp = (const __half2*)&bot;
#pragma unroll
        for (int j = 0; j < 4; j++) {
            __half2 hv = __hfma2(bp[j], wb2, __hmul2(tp[j], wt2));
            float2 f = __half22float2(hv);
            acc[2*j]   += f.x;
            acc[2*j+1] += f.y;
        }
    }

    // Merge left/right columns (partner lane q^2: same pixel, same octet)
#pragma unroll
    for (int rr = 0; rr < 8; rr++)
        acc[rr] += __shfl_xor_sync(0xffffffffu, acc[rr], 2);

    if (xq == 0) {
        // out layout (B,L,C,H,W); this lane owns channels [cq*8, cq*8+8)
        float* ob = out + ((size_t)(b * LL + t) * CC + cq * 8) * HW + p;
#pragma unroll
        for (int rr = 0; rr < 8; rr++) ob[rr * HW] = acc[rr];
    }
}

// ---------------------------------------------------------------------------
extern "C" void kernel_launch(void* const* d_in, const int* in_sizes, int n_in,
                              void* d_out, int out_size) {
    const float* flows  = (const float*)d_in[0];
    const float* images = (const float*)d_in[1];
    if (n_in >= 2 && in_sizes[0] > in_sizes[1]) {   // defensive: flows is smaller
        const float* tmp = flows; flows = images; images = tmp;
    }
    float* out = (float*)d_out;

    pad_kernel<<<(BB * LL * PCH + 255) / 256, 256>>>(images);
    main_kernel<<<BB * LL * 64, 256>>>(flows, out);
}